// round 13
// baseline (speedup 1.0000x reference)
#include <cuda_runtime.h>
#include <math.h>

#define CCH 256
#define BAT 16
#define HDIM 16
#define SPATIAL 16384      // 128*128
#define BC (BAT*CCH)       // 4096 planes
#define NBLK (BC*2)        // 8192 half-plane blocks
#define HALF4 2048         // float4s per half-plane
#define BLKS_PER_BATCH 512

// Scratch (device globals — no allocations allowed)
__device__ float g_hsum[NBLK];          // per-half-plane sum
__device__ float g_hsum2[NBLK];         // per-half-plane sumsq
__device__ float g_mask[BC];
__device__ unsigned int g_done[BAT];    // stats-halves-finished counters (monotonic)
__device__ unsigned int g_ready[BAT];   // mask-ready generation per batch (monotonic)
__device__ unsigned int g_tick;         // block tickets -> launch number (monotonic)

__device__ __forceinline__ float warp_sum(float v) {
#pragma unroll
    for (int o = 16; o > 0; o >>= 1) v += __shfl_xor_sync(0xffffffffu, v, o);
    return v;
}

__device__ __forceinline__ float dot4(float4 a, float4 b, float acc) {
    acc = fmaf(a.x, b.x, acc);
    acc = fmaf(a.y, b.y, acc);
    acc = fmaf(a.z, b.z, acc);
    return fmaf(a.w, b.w, acc);
}

// ---------------------------------------------------------------------------
// MLP chain for one batch element. First combines the 512 half-plane sums of
// batch b into per-plane std/mean (thread t -> plane b*256+t), then the SE /
// bottleneck chain. Executed by ONE 256-thread block (the batch's last one).
// ---------------------------------------------------------------------------
__device__ void mlp_block(
    int b, int tid,
    const float* __restrict__ sw1, const float* __restrict__ sb1,
    const float* __restrict__ sw2, const float* __restrict__ sb2,
    const float* __restrict__ mw1, const float* __restrict__ mb1,
    const float* __restrict__ mw2, const float* __restrict__ mb2,
    const float* __restrict__ bw,  const float* __restrict__ bb,
    const float* __restrict__ fw1, const float* __restrict__ fb1,
    const float* __restrict__ fw2, const float* __restrict__ fb2)
{
    const int w = tid >> 5, l = tid & 31;

    __shared__ float sdesc[2 * CCH];   // [std(256) | mean(256)]
    __shared__ float h[2 * HDIM];
    __shared__ float fused[2 * CCH];
    __shared__ float bott[CCH];
    __shared__ float fh[HDIM];

    // combine halves -> mean/std for this thread's plane
    {
        const int p = b * CCH + tid;
        const float ts  = g_hsum[2 * p]  + g_hsum[2 * p + 1];
        const float ts2 = g_hsum2[2 * p] + g_hsum2[2 * p + 1];
        const float inv = 1.f / (float)SPATIAL;
        const float mean = ts * inv;
        const float var  = ts2 * inv - mean * mean;
        sdesc[tid]       = sqrtf(fmaxf(var, 0.f));
        sdesc[CCH + tid] = mean;
    }
    __syncthreads();

    const float4* sdesc4 = (const float4*)sdesc;

    // SE hidden layers: 32 outputs (16 std + 16 mean).
#pragma unroll
    for (int j = 0; j < 4; j++) {
        const int o  = w * 4 + j;
        const int hh = o & (HDIM - 1);
        const float4* w1 = (const float4*)(((o < HDIM) ? sw1 : mw1) + hh * CCH);
        const float4* d  = (o < HDIM) ? sdesc4 : (sdesc4 + CCH / 4);
        float acc = 0.f;
#pragma unroll
        for (int k = 0; k < 2; k++)
            acc = dot4(w1[k * 32 + l], d[k * 32 + l], acc);
        acc = warp_sum(acc);
        if (l == 0) {
            const float bias = (o < HDIM) ? sb1[hh] : mb1[hh];
            h[o] = fmaxf(acc + bias, 0.f);
        }
    }
    __syncthreads();

    // SE output layers -> fused [512].
    {
        float a1 = sb2[tid], a2 = mb2[tid];
        const float4* s2 = (const float4*)(sw2 + tid * HDIM);
        const float4* m2 = (const float4*)(mw2 + tid * HDIM);
        const float4* h4a = (const float4*)h;
        const float4* h4b = (const float4*)(h + HDIM);
#pragma unroll
        for (int q = 0; q < 4; q++) {
            a1 = dot4(s2[q], h4a[q], a1);
            a2 = dot4(m2[q], h4b[q], a2);
        }
        fused[tid]       = a1;
        fused[CCH + tid] = a2;
    }
    __syncthreads();

    // Bottleneck 512 -> 256 + relu.
    const float4* fused4 = (const float4*)fused;
    for (int r = 0; r < 32; r += 2) {
        const int c0 = w + r * 8;
        const int c1 = w + (r + 1) * 8;
        const float4* b0 = (const float4*)(bw + c0 * (2 * CCH));
        const float4* b1 = (const float4*)(bw + c1 * (2 * CCH));
        float a0 = 0.f, a1 = 0.f;
#pragma unroll
        for (int k = 0; k < 4; k++) {
            const float4 f = fused4[k * 32 + l];
            a0 = dot4(b0[k * 32 + l], f, a0);
            a1 = dot4(b1[k * 32 + l], f, a1);
        }
        a0 = warp_sum(a0);
        a1 = warp_sum(a1);
        if (l == 0) {
            bott[c0] = fmaxf(a0 + bb[c0], 0.f);
            bott[c1] = fmaxf(a1 + bb[c1], 0.f);
        }
    }
    __syncthreads();

    // Final SE hidden: 16 outputs.
    const float4* bott4 = (const float4*)bott;
#pragma unroll
    for (int j = 0; j < 2; j++) {
        const int o = w * 2 + j;
        const float4* w1 = (const float4*)(fw1 + o * CCH);
        float acc = 0.f;
#pragma unroll
        for (int k = 0; k < 2; k++)
            acc = dot4(w1[k * 32 + l], bott4[k * 32 + l], acc);
        acc = warp_sum(acc);
        if (l == 0) fh[o] = fmaxf(acc + fb1[o], 0.f);
    }
    __syncthreads();

    // Final SE output + sigmoid -> mask.
    {
        float acc = fb2[tid];
        const float4* f2  = (const float4*)(fw2 + tid * HDIM);
        const float4* fh4 = (const float4*)fh;
#pragma unroll
        for (int q = 0; q < 4; q++) acc = dot4(f2[q], fh4[q], acc);
        g_mask[b * CCH + tid] = 1.f / (1.f + expf(-acc));
    }
}

// ---------------------------------------------------------------------------
// One block per HALF-PLANE (8192 blocks). Load half-plane into dynamic smem
// (x read from HBM exactly once), reduce sums, last-block-per-batch runs the
// MLP and publishes g_ready[b]; everyone waits, then applies FROM SMEM and
// streams out with write-through stores. LTS traffic: 512 MiB total.
// Deadlock-free: dispatch is in bid order; spinners of a batch hold <=511 of
// the >=592 resident slots (4 blocks/SM x 148), so the batch's last block
// always dispatches; Phase A needs no flag -> flag always gets set.
// ---------------------------------------------------------------------------
extern __shared__ float4 sdata[];   // HALF4 = 2048 float4 (32 KiB)

__global__ void __launch_bounds__(256, 4) fused_kernel(
    const float* __restrict__ x, float* __restrict__ out,
    const float* __restrict__ sw1, const float* __restrict__ sb1,
    const float* __restrict__ sw2, const float* __restrict__ sb2,
    const float* __restrict__ mw1, const float* __restrict__ mb1,
    const float* __restrict__ mw2, const float* __restrict__ mb2,
    const float* __restrict__ bw,  const float* __restrict__ bb,
    const float* __restrict__ fw1, const float* __restrict__ fb1,
    const float* __restrict__ fw2, const float* __restrict__ fb2)
{
    const int tid   = threadIdx.x;
    const int bid   = blockIdx.x;
    const int plane = bid >> 1;
    const int half  = bid & 1;
    const int b     = plane >> 8;

    __shared__ unsigned int sN;
    if (tid == 0) sN = atomicAdd(&g_tick, 1u) / NBLK + 1u;
    __syncthreads();
    const unsigned int N = sN;

    // ---- Phase A: load half-plane to smem + partial sums -----------------
    const size_t base = (size_t)plane * (SPATIAL / 4) + half * HALF4 + tid;
    const float4* __restrict__ xp = (const float4*)x + base;

    float s = 0.f, s2 = 0.f;
#pragma unroll
    for (int i = 0; i < 8; i++) {
        float4 v = __ldcs(&xp[i * 256]);
        sdata[i * 256 + tid] = v;
        s  += (v.x + v.y) + (v.z + v.w);
        s2 += (v.x * v.x + v.y * v.y) + (v.z * v.z + v.w * v.w);
    }
    s  = warp_sum(s);
    s2 = warp_sum(s2);
    __shared__ float ws[8], ws2[8];
    const int w = tid >> 5, l = tid & 31;
    if (l == 0) { ws[w] = s; ws2[w] = s2; }
    __syncthreads();

    __shared__ bool is_last;
    if (tid == 0) {
        float ts = 0.f, ts2 = 0.f;
#pragma unroll
        for (int i = 0; i < 8; i++) { ts += ws[i]; ts2 += ws2[i]; }
        g_hsum[bid]  = ts;
        g_hsum2[bid] = ts2;
        __threadfence();                        // publish sums before counting
        unsigned int cnt = atomicAdd(&g_done[b], 1u) + 1u;
        is_last = ((cnt & (BLKS_PER_BATCH - 1u)) == 0u);   // replay-safe
        if (is_last) __threadfence();           // acquire others' sums
    }
    __syncthreads();

    // ---- Phase B: last block per batch computes mask ---------------------
    if (is_last) {
        mlp_block(b, tid, sw1, sb1, sw2, sb2, mw1, mb1, mw2, mb2,
                  bw, bb, fw1, fb1, fw2, fb2);
        __syncthreads();                        // all mask stores done
        if (tid == 0) {
            __threadfence();                    // publish mask before flag
            atomicAdd(&g_ready[b], 1u);         // becomes N
        }
    }

    // ---- Phase C: wait for mask, apply from smem -------------------------
    if (tid == 0) {
        while (atomicAdd(&g_ready[b], 0u) < N) __nanosleep(128);
    }
    __syncthreads();
    __threadfence();                            // acquire mask writes

    const float m = g_mask[plane];
    float4* __restrict__ op = (float4*)out + base;
#pragma unroll
    for (int i = 0; i < 8; i++) {
        float4 t = sdata[i * 256 + tid];
        t.x *= m; t.y *= m; t.z *= m; t.w *= m;
        __stwt(&op[i * 256], t);
    }
}

extern "C" void kernel_launch(void* const* d_in, const int* in_sizes, int n_in,
                              void* d_out, int out_size) {
    const float* x   = (const float*)d_in[0];
    const float* sw1 = (const float*)d_in[1];
    const float* sb1 = (const float*)d_in[2];
    const float* sw2 = (const float*)d_in[3];
    const float* sb2 = (const float*)d_in[4];
    const float* mw1 = (const float*)d_in[5];
    const float* mb1 = (const float*)d_in[6];
    const float* mw2 = (const float*)d_in[7];
    const float* mb2 = (const float*)d_in[8];
    const float* bw  = (const float*)d_in[9];
    const float* bb  = (const float*)d_in[10];
    const float* fw1 = (const float*)d_in[11];
    const float* fb1 = (const float*)d_in[12];
    const float* fw2 = (const float*)d_in[13];
    const float* fb2 = (const float*)d_in[14];
    float* out = (float*)d_out;

    fused_kernel<<<NBLK, 256, HALF4 * sizeof(float4)>>>(x, out,
        sw1, sb1, sw2, sb2, mw1, mb1, mw2, mb2,
        bw, bb, fw1, fb1, fw2, fb2);
}

// round 14
// speedup vs baseline: 1.6028x; 1.6028x over previous
#include <cuda_runtime.h>
#include <math.h>

#define CCH 256
#define BAT 16
#define HDIM 16
#define SPATIAL 16384      // 128*128
#define BC (BAT*CCH)       // 4096 planes
#define NUNIT (BC*2)       // 8192 half-plane units
#define HALF4 2048         // float4s per half-plane
#define UNITS_PER_BATCH 512
#define PIPE  UNITS_PER_BATCH              // apply lags stats by one batch
#define TOTAL_BLKS (NUNIT + PIPE)          // 8704

// Scratch (device globals — no allocations allowed)
__device__ float g_hsum[NUNIT];         // per-half-plane sum
__device__ float g_hsum2[NUNIT];        // per-half-plane sumsq
__device__ float g_mask[BC];
__device__ unsigned int g_done[BAT];    // stats-halves-finished (monotonic)
__device__ unsigned int g_ready[BAT];   // mask-ready generation (monotonic)
__device__ unsigned int g_tick;         // block tickets -> launch number

__device__ __forceinline__ float warp_sum(float v) {
#pragma unroll
    for (int o = 16; o > 0; o >>= 1) v += __shfl_xor_sync(0xffffffffu, v, o);
    return v;
}

__device__ __forceinline__ float dot4(float4 a, float4 b, float acc) {
    acc = fmaf(a.x, b.x, acc);
    acc = fmaf(a.y, b.y, acc);
    acc = fmaf(a.z, b.z, acc);
    return fmaf(a.w, b.w, acc);
}

// ---------------------------------------------------------------------------
// MLP chain for one batch element (combines 512 half-plane sums first).
// Executed by ONE 256-thread block (the batch's last stats block).
// ---------------------------------------------------------------------------
__device__ void mlp_block(
    int b, int tid,
    const float* __restrict__ sw1, const float* __restrict__ sb1,
    const float* __restrict__ sw2, const float* __restrict__ sb2,
    const float* __restrict__ mw1, const float* __restrict__ mb1,
    const float* __restrict__ mw2, const float* __restrict__ mb2,
    const float* __restrict__ bw,  const float* __restrict__ bb,
    const float* __restrict__ fw1, const float* __restrict__ fb1,
    const float* __restrict__ fw2, const float* __restrict__ fb2)
{
    const int w = tid >> 5, l = tid & 31;

    __shared__ float sdesc[2 * CCH];   // [std(256) | mean(256)]
    __shared__ float h[2 * HDIM];
    __shared__ float fused[2 * CCH];
    __shared__ float bott[CCH];
    __shared__ float fh[HDIM];

    // combine halves -> mean/std for this thread's plane
    {
        const int p = b * CCH + tid;
        const float ts  = g_hsum[2 * p]  + g_hsum[2 * p + 1];
        const float ts2 = g_hsum2[2 * p] + g_hsum2[2 * p + 1];
        const float inv = 1.f / (float)SPATIAL;
        const float mean = ts * inv;
        const float var  = ts2 * inv - mean * mean;
        sdesc[tid]       = sqrtf(fmaxf(var, 0.f));
        sdesc[CCH + tid] = mean;
    }
    __syncthreads();

    const float4* sdesc4 = (const float4*)sdesc;

    // SE hidden layers: 32 outputs (16 std + 16 mean).
#pragma unroll
    for (int j = 0; j < 4; j++) {
        const int o  = w * 4 + j;
        const int hh = o & (HDIM - 1);
        const float4* w1 = (const float4*)(((o < HDIM) ? sw1 : mw1) + hh * CCH);
        const float4* d  = (o < HDIM) ? sdesc4 : (sdesc4 + CCH / 4);
        float acc = 0.f;
#pragma unroll
        for (int k = 0; k < 2; k++)
            acc = dot4(w1[k * 32 + l], d[k * 32 + l], acc);
        acc = warp_sum(acc);
        if (l == 0) {
            const float bias = (o < HDIM) ? sb1[hh] : mb1[hh];
            h[o] = fmaxf(acc + bias, 0.f);
        }
    }
    __syncthreads();

    // SE output layers -> fused [512].
    {
        float a1 = sb2[tid], a2 = mb2[tid];
        const float4* s2 = (const float4*)(sw2 + tid * HDIM);
        const float4* m2 = (const float4*)(mw2 + tid * HDIM);
        const float4* h4a = (const float4*)h;
        const float4* h4b = (const float4*)(h + HDIM);
#pragma unroll
        for (int q = 0; q < 4; q++) {
            a1 = dot4(s2[q], h4a[q], a1);
            a2 = dot4(m2[q], h4b[q], a2);
        }
        fused[tid]       = a1;
        fused[CCH + tid] = a2;
    }
    __syncthreads();

    // Bottleneck 512 -> 256 + relu.
    const float4* fused4 = (const float4*)fused;
    for (int r = 0; r < 32; r += 2) {
        const int c0 = w + r * 8;
        const int c1 = w + (r + 1) * 8;
        const float4* b0 = (const float4*)(bw + c0 * (2 * CCH));
        const float4* b1 = (const float4*)(bw + c1 * (2 * CCH));
        float a0 = 0.f, a1 = 0.f;
#pragma unroll
        for (int k = 0; k < 4; k++) {
            const float4 f = fused4[k * 32 + l];
            a0 = dot4(b0[k * 32 + l], f, a0);
            a1 = dot4(b1[k * 32 + l], f, a1);
        }
        a0 = warp_sum(a0);
        a1 = warp_sum(a1);
        if (l == 0) {
            bott[c0] = fmaxf(a0 + bb[c0], 0.f);
            bott[c1] = fmaxf(a1 + bb[c1], 0.f);
        }
    }
    __syncthreads();

    // Final SE hidden: 16 outputs.
    const float4* bott4 = (const float4*)bott;
#pragma unroll
    for (int j = 0; j < 2; j++) {
        const int o = w * 2 + j;
        const float4* w1 = (const float4*)(fw1 + o * CCH);
        float acc = 0.f;
#pragma unroll
        for (int k = 0; k < 2; k++)
            acc = dot4(w1[k * 32 + l], bott4[k * 32 + l], acc);
        acc = warp_sum(acc);
        if (l == 0) fh[o] = fmaxf(acc + fb1[o], 0.f);
    }
    __syncthreads();

    // Final SE output + sigmoid -> mask.
    {
        float acc = fb2[tid];
        const float4* f2  = (const float4*)(fw2 + tid * HDIM);
        const float4* fh4 = (const float4*)fh;
#pragma unroll
        for (int q = 0; q < 4; q++) acc = dot4(f2[q], fh4[q], acc);
        g_mask[b * CCH + tid] = 1.f / (1.f + expf(-acc));
    }
}

// ---------------------------------------------------------------------------
// Software-pipelined fused kernel, 8704 blocks:
//   block i < 8192       : stats for unit i (plain loads seed L2)
//   block i >= 512       : apply for unit i-512 (one batch behind)
// Apply waits only on the PREVIOUS batch's mask -> dispatched >=512 bids
// earlier; resident window (4 blocks/SM x 148 = 592) > 512, and stats never
// blocks, so progress is guaranteed. Monotonic counters -> replay-safe.
// Apply reads hit L2 (data streamed ~16 MiB earlier): DRAM ~512 MiB total.
// ---------------------------------------------------------------------------
__global__ void __launch_bounds__(256, 4) fused_kernel(
    const float* __restrict__ x, float* __restrict__ out,
    const float* __restrict__ sw1, const float* __restrict__ sb1,
    const float* __restrict__ sw2, const float* __restrict__ sb2,
    const float* __restrict__ mw1, const float* __restrict__ mb1,
    const float* __restrict__ mw2, const float* __restrict__ mb2,
    const float* __restrict__ bw,  const float* __restrict__ bb,
    const float* __restrict__ fw1, const float* __restrict__ fb1,
    const float* __restrict__ fw2, const float* __restrict__ fb2)
{
    const int tid = threadIdx.x;
    const int bid = blockIdx.x;

    __shared__ unsigned int sN;
    if (tid == 0) sN = atomicAdd(&g_tick, 1u) / TOTAL_BLKS + 1u;
    __syncthreads();
    const unsigned int N = sN;

    // ---- Stage 1: stats for unit 'bid' -----------------------------------
    if (bid < NUNIT) {
        const int u     = bid;
        const int plane = u >> 1;
        const int half  = u & 1;
        const int b     = u >> 9;           // batch = u / 512
        const size_t base = (size_t)plane * (SPATIAL / 4) + half * HALF4 + tid;
        const float4* __restrict__ xp = (const float4*)x + base;

        float s = 0.f, s2 = 0.f;
#pragma unroll
        for (int i = 0; i < 8; i++) {
            float4 v = xp[i * 256];         // plain load: seed L2 for apply
            s  += (v.x + v.y) + (v.z + v.w);
            s2 += (v.x * v.x + v.y * v.y) + (v.z * v.z + v.w * v.w);
        }
        s  = warp_sum(s);
        s2 = warp_sum(s2);
        __shared__ float ws[8], ws2[8];
        const int w = tid >> 5, l = tid & 31;
        if (l == 0) { ws[w] = s; ws2[w] = s2; }
        __syncthreads();

        __shared__ bool is_last;
        if (tid == 0) {
            float ts = 0.f, ts2 = 0.f;
#pragma unroll
            for (int i = 0; i < 8; i++) { ts += ws[i]; ts2 += ws2[i]; }
            g_hsum[u]  = ts;
            g_hsum2[u] = ts2;
            __threadfence();                // publish sums before counting
            unsigned int cnt = atomicAdd(&g_done[b], 1u) + 1u;
            is_last = ((cnt & (UNITS_PER_BATCH - 1u)) == 0u);
            if (is_last) __threadfence();   // acquire others' sums
        }
        __syncthreads();

        if (is_last) {
            mlp_block(b, tid, sw1, sb1, sw2, sb2, mw1, mb1, mw2, mb2,
                      bw, bb, fw1, fb1, fw2, fb2);
            __syncthreads();                // all mask stores done
            if (tid == 0) {
                __threadfence();            // publish mask before flag
                atomicAdd(&g_ready[b], 1u); // becomes N
            }
        }
    }

    // ---- Stage 2: apply for unit 'bid - 512' ------------------------------
    if (bid >= PIPE) {
        const int u     = bid - PIPE;
        const int plane = u >> 1;
        const int half  = u & 1;
        const int b     = u >> 9;

        if (tid == 0) {
            while (atomicAdd(&g_ready[b], 0u) < N) __nanosleep(64);
        }
        __syncthreads();
        __threadfence();                    // acquire mask writes

        const float m = g_mask[plane];
        const size_t base = (size_t)plane * (SPATIAL / 4) + half * HALF4 + tid;
        const float4* __restrict__ xp = (const float4*)x + base;
        float4* __restrict__ op = (float4*)out + base;

        float4 v[8];
#pragma unroll
        for (int i = 0; i < 8; i++) v[i] = __ldcs(&xp[i * 256]);
#pragma unroll
        for (int i = 0; i < 8; i++) {
            float4 t = v[i];
            t.x *= m; t.y *= m; t.z *= m; t.w *= m;
            __stwt(&op[i * 256], t);
        }
    }
}

extern "C" void kernel_launch(void* const* d_in, const int* in_sizes, int n_in,
                              void* d_out, int out_size) {
    const float* x   = (const float*)d_in[0];
    const float* sw1 = (const float*)d_in[1];
    const float* sb1 = (const float*)d_in[2];
    const float* sw2 = (const float*)d_in[3];
    const float* sb2 = (const float*)d_in[4];
    const float* mw1 = (const float*)d_in[5];
    const float* mb1 = (const float*)d_in[6];
    const float* mw2 = (const float*)d_in[7];
    const float* mb2 = (const float*)d_in[8];
    const float* bw  = (const float*)d_in[9];
    const float* bb  = (const float*)d_in[10];
    const float* fw1 = (const float*)d_in[11];
    const float* fb1 = (const float*)d_in[12];
    const float* fw2 = (const float*)d_in[13];
    const float* fb2 = (const float*)d_in[14];
    float* out = (float*)d_out;

    fused_kernel<<<TOTAL_BLKS, 256>>>(x, out,
        sw1, sb1, sw2, sb2, mw1, mb1, mw2, mb2,
        bw, bb, fw1, fb1, fw2, fb2);
}

// round 15
// speedup vs baseline: 2.4618x; 1.5360x over previous
#include <cuda_runtime.h>
#include <math.h>

#define CCH 256
#define BAT 16
#define HDIM 16
#define SPATIAL 16384      // 128*128
#define BC (BAT*CCH)       // 4096 planes

// Scratch (device globals — no allocations allowed)
__device__ float g_mean[BC];
__device__ float g_std[BC];
__device__ float g_mask[BC];
__device__ unsigned int g_done[BAT];   // monotonic last-block counters

__device__ __forceinline__ float warp_sum(float v) {
#pragma unroll
    for (int o = 16; o > 0; o >>= 1) v += __shfl_xor_sync(0xffffffffu, v, o);
    return v;
}

__device__ __forceinline__ float dot4(float4 a, float4 b, float acc) {
    acc = fmaf(a.x, b.x, acc);
    acc = fmaf(a.y, b.y, acc);
    acc = fmaf(a.z, b.z, acc);
    return fmaf(a.w, b.w, acc);
}

// ---------------------------------------------------------------------------
// MLP chain for one batch element, executed by one 256-thread block.
// ---------------------------------------------------------------------------
__device__ void mlp_block(
    int b, int tid,
    const float* __restrict__ sw1, const float* __restrict__ sb1,
    const float* __restrict__ sw2, const float* __restrict__ sb2,
    const float* __restrict__ mw1, const float* __restrict__ mb1,
    const float* __restrict__ mw2, const float* __restrict__ mb2,
    const float* __restrict__ bw,  const float* __restrict__ bb,
    const float* __restrict__ fw1, const float* __restrict__ fb1,
    const float* __restrict__ fw2, const float* __restrict__ fb2)
{
    const int w = tid >> 5, l = tid & 31;

    __shared__ float sdesc[2 * CCH];   // [std(256) | mean(256)]
    __shared__ float h[2 * HDIM];
    __shared__ float fused[2 * CCH];
    __shared__ float bott[CCH];
    __shared__ float fh[HDIM];

    sdesc[tid]       = g_std[b * CCH + tid];
    sdesc[CCH + tid] = g_mean[b * CCH + tid];
    __syncthreads();

    const float4* sdesc4 = (const float4*)sdesc;

    // SE hidden layers: 32 outputs (16 std + 16 mean).
#pragma unroll
    for (int j = 0; j < 4; j++) {
        const int o  = w * 4 + j;
        const int hh = o & (HDIM - 1);
        const float4* w1 = (const float4*)(((o < HDIM) ? sw1 : mw1) + hh * CCH);
        const float4* d  = (o < HDIM) ? sdesc4 : (sdesc4 + CCH / 4);
        float acc = 0.f;
#pragma unroll
        for (int k = 0; k < 2; k++)
            acc = dot4(w1[k * 32 + l], d[k * 32 + l], acc);
        acc = warp_sum(acc);
        if (l == 0) {
            const float bias = (o < HDIM) ? sb1[hh] : mb1[hh];
            h[o] = fmaxf(acc + bias, 0.f);
        }
    }
    __syncthreads();

    // SE output layers -> fused [512].
    {
        float a1 = sb2[tid], a2 = mb2[tid];
        const float4* s2 = (const float4*)(sw2 + tid * HDIM);
        const float4* m2 = (const float4*)(mw2 + tid * HDIM);
        const float4* h4a = (const float4*)h;
        const float4* h4b = (const float4*)(h + HDIM);
#pragma unroll
        for (int q = 0; q < 4; q++) {
            a1 = dot4(s2[q], h4a[q], a1);
            a2 = dot4(m2[q], h4b[q], a2);
        }
        fused[tid]       = a1;
        fused[CCH + tid] = a2;
    }
    __syncthreads();

    // Bottleneck 512 -> 256 + relu.
    const float4* fused4 = (const float4*)fused;
    for (int r = 0; r < 32; r += 2) {
        const int c0 = w + r * 8;
        const int c1 = w + (r + 1) * 8;
        const float4* b0 = (const float4*)(bw + c0 * (2 * CCH));
        const float4* b1 = (const float4*)(bw + c1 * (2 * CCH));
        float a0 = 0.f, a1 = 0.f;
#pragma unroll
        for (int k = 0; k < 4; k++) {
            const float4 f = fused4[k * 32 + l];
            a0 = dot4(b0[k * 32 + l], f, a0);
            a1 = dot4(b1[k * 32 + l], f, a1);
        }
        a0 = warp_sum(a0);
        a1 = warp_sum(a1);
        if (l == 0) {
            bott[c0] = fmaxf(a0 + bb[c0], 0.f);
            bott[c1] = fmaxf(a1 + bb[c1], 0.f);
        }
    }
    __syncthreads();

    // Final SE hidden: 16 outputs.
    const float4* bott4 = (const float4*)bott;
#pragma unroll
    for (int j = 0; j < 2; j++) {
        const int o = w * 2 + j;
        const float4* w1 = (const float4*)(fw1 + o * CCH);
        float acc = 0.f;
#pragma unroll
        for (int k = 0; k < 2; k++)
            acc = dot4(w1[k * 32 + l], bott4[k * 32 + l], acc);
        acc = warp_sum(acc);
        if (l == 0) fh[o] = fmaxf(acc + fb1[o], 0.f);
    }
    __syncthreads();

    // Final SE output + sigmoid -> mask.
    {
        float acc = fb2[tid];
        const float4* f2  = (const float4*)(fw2 + tid * HDIM);
        const float4* fh4 = (const float4*)fh;
#pragma unroll
        for (int q = 0; q < 4; q++) acc = dot4(f2[q], fh4[q], acc);
        g_mask[b * CCH + tid] = 1.f / (1.f + expf(-acc));
    }
}

// ---------------------------------------------------------------------------
// PRIMARY: stats over all 4096 planes + fused MLP (last block per batch).
// Each block triggers programmatic launch completion right after its own
// stats work, so the dependent apply kernel can start prefetching during the
// stats drain + MLP tail.
// ---------------------------------------------------------------------------
__global__ void __launch_bounds__(256) stats_mlp_kernel(
    const float* __restrict__ x,
    const float* __restrict__ sw1, const float* __restrict__ sb1,
    const float* __restrict__ sw2, const float* __restrict__ sb2,
    const float* __restrict__ mw1, const float* __restrict__ mb1,
    const float* __restrict__ mw2, const float* __restrict__ mb2,
    const float* __restrict__ bw,  const float* __restrict__ bb,
    const float* __restrict__ fw1, const float* __restrict__ fb1,
    const float* __restrict__ fw2, const float* __restrict__ fb2)
{
    const int tid = threadIdx.x;
    const int bc  = blockIdx.x;
    const int b   = bc >> 8;               // batch index
    const float4* __restrict__ xp = (const float4*)(x + (size_t)bc * SPATIAL);

    float s = 0.f, s2 = 0.f;
#pragma unroll
    for (int i = 0; i < SPATIAL / 4 / 256; i++) {
        float4 v = xp[i * 256 + tid];      // cached: seed L2 for apply pass
        s  += (v.x + v.y) + (v.z + v.w);
        s2 += (v.x * v.x + v.y * v.y) + (v.z * v.z + v.w * v.w);
    }
    s  = warp_sum(s);
    s2 = warp_sum(s2);
    __shared__ float ws[8], ws2[8];
    const int w = tid >> 5, l = tid & 31;
    if (l == 0) { ws[w] = s; ws2[w] = s2; }
    __syncthreads();

    __shared__ bool is_last;
    if (tid == 0) {
        float ts = 0.f, ts2 = 0.f;
#pragma unroll
        for (int i = 0; i < 8; i++) { ts += ws[i]; ts2 += ws2[i]; }
        const float inv = 1.f / (float)SPATIAL;
        float mean = ts * inv;
        float var  = ts2 * inv - mean * mean;
        g_mean[bc] = mean;
        g_std[bc]  = sqrtf(fmaxf(var, 0.f));
        __threadfence();                    // publish stats before counting in
        unsigned int cnt = atomicAdd(&g_done[b], 1u) + 1u;
        is_last = ((cnt & 255u) == 0u);     // monotonic: replay-safe
        if (is_last) __threadfence();       // acquire others' stats writes
    }
    __syncthreads();

    // Allow the dependent apply kernel to launch; its grid-dependency sync
    // still waits for THIS ENTIRE GRID (incl. MLP below) before it consumes
    // the mask, so this only enables prefetch overlap, not a race.
    cudaTriggerProgrammaticLaunchCompletion();

    if (is_last) {
        mlp_block(b, tid, sw1, sb1, sw2, sb2, mw1, mb1, mw2, mb2,
                  bw, bb, fw1, fb1, fw2, fb2);
    }
}

// ---------------------------------------------------------------------------
// SECONDARY (PDL): prefetch this block's 32 KiB of x into registers (x is
// read-only -> safe before the dependency), THEN wait for the primary grid
// (mask ready + visible), then scale + streaming store. Reverse plane order
// keeps the R9 L2-tail hits. No spin loops anywhere.
// ---------------------------------------------------------------------------
__global__ void __launch_bounds__(256) apply_kernel(const float* __restrict__ x,
                                                    float* __restrict__ out) {
    const int plane = BC - 1 - (blockIdx.x >> 1);      // reverse plane order
    const int half  = blockIdx.x & 1;
    const size_t base = (size_t)plane * (SPATIAL / 4) + half * 2048 + threadIdx.x;
    const float4* __restrict__ xp = (const float4*)x + base;
    float4* __restrict__ op = (float4*)out + base;

    float4 v[8];
#pragma unroll
    for (int i = 0; i < 8; i++) v[i] = __ldcs(&xp[i * 256]);

    cudaGridDependencySynchronize();       // primary grid done, mask visible

    const float m = g_mask[plane];
#pragma unroll
    for (int i = 0; i < 8; i++) {
        float4 t = v[i];
        t.x *= m; t.y *= m; t.z *= m; t.w *= m;
        __stwt(&op[i * 256], t);
    }
}

extern "C" void kernel_launch(void* const* d_in, const int* in_sizes, int n_in,
                              void* d_out, int out_size) {
    const float* x   = (const float*)d_in[0];
    const float* sw1 = (const float*)d_in[1];
    const float* sb1 = (const float*)d_in[2];
    const float* sw2 = (const float*)d_in[3];
    const float* sb2 = (const float*)d_in[4];
    const float* mw1 = (const float*)d_in[5];
    const float* mb1 = (const float*)d_in[6];
    const float* mw2 = (const float*)d_in[7];
    const float* mb2 = (const float*)d_in[8];
    const float* bw  = (const float*)d_in[9];
    const float* bb  = (const float*)d_in[10];
    const float* fw1 = (const float*)d_in[11];
    const float* fb1 = (const float*)d_in[12];
    const float* fw2 = (const float*)d_in[13];
    const float* fb2 = (const float*)d_in[14];
    float* out = (float*)d_out;

    // Primary launch (normal).
    stats_mlp_kernel<<<BC, 256>>>(x,
        sw1, sb1, sw2, sb2, mw1, mb1, mw2, mb2,
        bw, bb, fw1, fb1, fw2, fb2);

    // Secondary launch with Programmatic Dependent Launch.
    cudaLaunchAttribute attrs[1];
    attrs[0].id = cudaLaunchAttributeProgrammaticStreamSerialization;
    attrs[0].val.programmaticStreamSerializationAllowed = 1;

    cudaLaunchConfig_t cfg = {};
    cfg.gridDim  = dim3(BC * 2, 1, 1);
    cfg.blockDim = dim3(256, 1, 1);
    cfg.dynamicSmemBytes = 0;
    cfg.stream = 0;            // same (capture) stream as the <<<>>> launch
    cfg.attrs = attrs;
    cfg.numAttrs = 1;

    cudaLaunchKernelEx(&cfg, apply_kernel, x, (float*)out);
}

// round 16
// speedup vs baseline: 2.4946x; 1.0133x over previous
#include <cuda_runtime.h>
#include <math.h>

#define CCH 256
#define BAT 16
#define HDIM 16
#define SPATIAL 16384      // 128*128
#define BC (BAT*CCH)       // 4096 planes
#define NUNIT (BC*2)       // 8192 half-plane units
#define HALF4 2048         // float4s per half-plane
#define UNITS_PER_BATCH 512

// Scratch (device globals — no allocations allowed)
__device__ float g_hsum[NUNIT];         // per-half-plane sum
__device__ float g_hsum2[NUNIT];        // per-half-plane sumsq
__device__ float g_mask[BC];
__device__ unsigned int g_done[BAT];    // monotonic last-block counters

__device__ __forceinline__ float warp_sum(float v) {
#pragma unroll
    for (int o = 16; o > 0; o >>= 1) v += __shfl_xor_sync(0xffffffffu, v, o);
    return v;
}

__device__ __forceinline__ float dot4(float4 a, float4 b, float acc) {
    acc = fmaf(a.x, b.x, acc);
    acc = fmaf(a.y, b.y, acc);
    acc = fmaf(a.z, b.z, acc);
    return fmaf(a.w, b.w, acc);
}

// ---------------------------------------------------------------------------
// MLP chain for one batch element: combine the 512 half-plane sums into
// per-plane std/mean, then SE/bottleneck chain. One 256-thread block.
// ---------------------------------------------------------------------------
__device__ void mlp_block(
    int b, int tid,
    const float* __restrict__ sw1, const float* __restrict__ sb1,
    const float* __restrict__ sw2, const float* __restrict__ sb2,
    const float* __restrict__ mw1, const float* __restrict__ mb1,
    const float* __restrict__ mw2, const float* __restrict__ mb2,
    const float* __restrict__ bw,  const float* __restrict__ bb,
    const float* __restrict__ fw1, const float* __restrict__ fb1,
    const float* __restrict__ fw2, const float* __restrict__ fb2)
{
    const int w = tid >> 5, l = tid & 31;

    __shared__ float sdesc[2 * CCH];   // [std(256) | mean(256)]
    __shared__ float h[2 * HDIM];
    __shared__ float fused[2 * CCH];
    __shared__ float bott[CCH];
    __shared__ float fh[HDIM];

    // combine halves -> mean/std for this thread's plane
    {
        const int p = b * CCH + tid;
        const float ts  = g_hsum[2 * p]  + g_hsum[2 * p + 1];
        const float ts2 = g_hsum2[2 * p] + g_hsum2[2 * p + 1];
        const float inv = 1.f / (float)SPATIAL;
        const float mean = ts * inv;
        const float var  = ts2 * inv - mean * mean;
        sdesc[tid]       = sqrtf(fmaxf(var, 0.f));
        sdesc[CCH + tid] = mean;
    }
    __syncthreads();

    const float4* sdesc4 = (const float4*)sdesc;

    // SE hidden layers: 32 outputs (16 std + 16 mean).
#pragma unroll
    for (int j = 0; j < 4; j++) {
        const int o  = w * 4 + j;
        const int hh = o & (HDIM - 1);
        const float4* w1 = (const float4*)(((o < HDIM) ? sw1 : mw1) + hh * CCH);
        const float4* d  = (o < HDIM) ? sdesc4 : (sdesc4 + CCH / 4);
        float acc = 0.f;
#pragma unroll
        for (int k = 0; k < 2; k++)
            acc = dot4(w1[k * 32 + l], d[k * 32 + l], acc);
        acc = warp_sum(acc);
        if (l == 0) {
            const float bias = (o < HDIM) ? sb1[hh] : mb1[hh];
            h[o] = fmaxf(acc + bias, 0.f);
        }
    }
    __syncthreads();

    // SE output layers -> fused [512].
    {
        float a1 = sb2[tid], a2 = mb2[tid];
        const float4* s2 = (const float4*)(sw2 + tid * HDIM);
        const float4* m2 = (const float4*)(mw2 + tid * HDIM);
        const float4* h4a = (const float4*)h;
        const float4* h4b = (const float4*)(h + HDIM);
#pragma unroll
        for (int q = 0; q < 4; q++) {
            a1 = dot4(s2[q], h4a[q], a1);
            a2 = dot4(m2[q], h4b[q], a2);
        }
        fused[tid]       = a1;
        fused[CCH + tid] = a2;
    }
    __syncthreads();

    // Bottleneck 512 -> 256 + relu.
    const float4* fused4 = (const float4*)fused;
    for (int r = 0; r < 32; r += 2) {
        const int c0 = w + r * 8;
        const int c1 = w + (r + 1) * 8;
        const float4* b0 = (const float4*)(bw + c0 * (2 * CCH));
        const float4* b1 = (const float4*)(bw + c1 * (2 * CCH));
        float a0 = 0.f, a1 = 0.f;
#pragma unroll
        for (int k = 0; k < 4; k++) {
            const float4 f = fused4[k * 32 + l];
            a0 = dot4(b0[k * 32 + l], f, a0);
            a1 = dot4(b1[k * 32 + l], f, a1);
        }
        a0 = warp_sum(a0);
        a1 = warp_sum(a1);
        if (l == 0) {
            bott[c0] = fmaxf(a0 + bb[c0], 0.f);
            bott[c1] = fmaxf(a1 + bb[c1], 0.f);
        }
    }
    __syncthreads();

    // Final SE hidden: 16 outputs.
    const float4* bott4 = (const float4*)bott;
#pragma unroll
    for (int j = 0; j < 2; j++) {
        const int o = w * 2 + j;
        const float4* w1 = (const float4*)(fw1 + o * CCH);
        float acc = 0.f;
#pragma unroll
        for (int k = 0; k < 2; k++)
            acc = dot4(w1[k * 32 + l], bott4[k * 32 + l], acc);
        acc = warp_sum(acc);
        if (l == 0) fh[o] = fmaxf(acc + fb1[o], 0.f);
    }
    __syncthreads();

    // Final SE output + sigmoid -> mask.
    {
        float acc = fb2[tid];
        const float4* f2  = (const float4*)(fw2 + tid * HDIM);
        const float4* fh4 = (const float4*)fh;
#pragma unroll
        for (int q = 0; q < 4; q++) acc = dot4(f2[q], fh4[q], acc);
        g_mask[b * CCH + tid] = 1.f / (1.f + expf(-acc));
    }
}

// ---------------------------------------------------------------------------
// PRIMARY: stats with apply's exact memory shape — 8192 half-plane blocks,
// 8 front-batched float4 loads/thread (the shape measured at 6.8 TB/s).
// Emits per-half partial sums; last unit per batch (monotonic counter) runs
// the MLP. Plain cached loads seed L2 tail for the reverse-order apply.
// ---------------------------------------------------------------------------
__global__ void __launch_bounds__(256) stats_mlp_kernel(
    const float* __restrict__ x,
    const float* __restrict__ sw1, const float* __restrict__ sb1,
    const float* __restrict__ sw2, const float* __restrict__ sb2,
    const float* __restrict__ mw1, const float* __restrict__ mb1,
    const float* __restrict__ mw2, const float* __restrict__ mb2,
    const float* __restrict__ bw,  const float* __restrict__ bb,
    const float* __restrict__ fw1, const float* __restrict__ fb1,
    const float* __restrict__ fw2, const float* __restrict__ fb2)
{
    const int tid   = threadIdx.x;
    const int u     = blockIdx.x;           // half-plane unit
    const int plane = u >> 1;
    const int half  = u & 1;
    const int b     = u >> 9;                // batch = u / 512
    const size_t base = (size_t)plane * (SPATIAL / 4) + half * HALF4 + tid;
    const float4* __restrict__ xp = (const float4*)x + base;

    float4 v[8];
#pragma unroll
    for (int i = 0; i < 8; i++) v[i] = xp[i * 256];   // front-batched, cached

    float s = 0.f, s2 = 0.f;
#pragma unroll
    for (int i = 0; i < 8; i++) {
        s  += (v[i].x + v[i].y) + (v[i].z + v[i].w);
        s2 += (v[i].x * v[i].x + v[i].y * v[i].y)
            + (v[i].z * v[i].z + v[i].w * v[i].w);
    }
    s  = warp_sum(s);
    s2 = warp_sum(s2);
    __shared__ float ws[8], ws2[8];
    const int w = tid >> 5, l = tid & 31;
    if (l == 0) { ws[w] = s; ws2[w] = s2; }
    __syncthreads();

    __shared__ bool is_last;
    if (tid == 0) {
        float ts = 0.f, ts2 = 0.f;
#pragma unroll
        for (int i = 0; i < 8; i++) { ts += ws[i]; ts2 += ws2[i]; }
        g_hsum[u]  = ts;
        g_hsum2[u] = ts2;
        __threadfence();                     // publish sums before counting in
        unsigned int cnt = atomicAdd(&g_done[b], 1u) + 1u;
        is_last = ((cnt & (UNITS_PER_BATCH - 1u)) == 0u);   // replay-safe
        if (is_last) __threadfence();        // acquire others' sums
    }
    __syncthreads();

    cudaTriggerProgrammaticLaunchCompletion();

    if (is_last) {
        mlp_block(b, tid, sw1, sb1, sw2, sb2, mw1, mb1, mw2, mb2,
                  bw, bb, fw1, fb1, fw2, fb2);
    }
}

// ---------------------------------------------------------------------------
// SECONDARY (PDL): unchanged proven apply — 79us @ 6.8 TB/s. Prefetch x,
// wait for the primary grid, scale, streaming store. Reverse plane order
// for L2-tail hits.
// ---------------------------------------------------------------------------
__global__ void __launch_bounds__(256) apply_kernel(const float* __restrict__ x,
                                                    float* __restrict__ out) {
    const int plane = BC - 1 - (blockIdx.x >> 1);      // reverse plane order
    const int half  = blockIdx.x & 1;
    const size_t base = (size_t)plane * (SPATIAL / 4) + half * HALF4 + threadIdx.x;
    const float4* __restrict__ xp = (const float4*)x + base;
    float4* __restrict__ op = (float4*)out + base;

    float4 v[8];
#pragma unroll
    for (int i = 0; i < 8; i++) v[i] = __ldcs(&xp[i * 256]);

    cudaGridDependencySynchronize();       // primary grid done, mask visible

    const float m = g_mask[plane];
#pragma unroll
    for (int i = 0; i < 8; i++) {
        float4 t = v[i];
        t.x *= m; t.y *= m; t.z *= m; t.w *= m;
        __stwt(&op[i * 256], t);
    }
}

extern "C" void kernel_launch(void* const* d_in, const int* in_sizes, int n_in,
                              void* d_out, int out_size) {
    const float* x   = (const float*)d_in[0];
    const float* sw1 = (const float*)d_in[1];
    const float* sb1 = (const float*)d_in[2];
    const float* sw2 = (const float*)d_in[3];
    const float* sb2 = (const float*)d_in[4];
    const float* mw1 = (const float*)d_in[5];
    const float* mb1 = (const float*)d_in[6];
    const float* mw2 = (const float*)d_in[7];
    const float* mb2 = (const float*)d_in[8];
    const float* bw  = (const float*)d_in[9];
    const float* bb  = (const float*)d_in[10];
    const float* fw1 = (const float*)d_in[11];
    const float* fb1 = (const float*)d_in[12];
    const float* fw2 = (const float*)d_in[13];
    const float* fb2 = (const float*)d_in[14];
    float* out = (float*)d_out;

    stats_mlp_kernel<<<NUNIT, 256>>>(x,
        sw1, sb1, sw2, sb2, mw1, mb1, mw2, mb2,
        bw, bb, fw1, fb1, fw2, fb2);

    cudaLaunchAttribute attrs[1];
    attrs[0].id = cudaLaunchAttributeProgrammaticStreamSerialization;
    attrs[0].val.programmaticStreamSerializationAllowed = 1;

    cudaLaunchConfig_t cfg = {};
    cfg.gridDim  = dim3(BC * 2, 1, 1);
    cfg.blockDim = dim3(256, 1, 1);
    cfg.dynamicSmemBytes = 0;
    cfg.stream = 0;
    cfg.attrs = attrs;
    cfg.numAttrs = 1;

    cudaLaunchKernelEx(&cfg, apply_kernel, x, (float*)out);
}